// round 2
// baseline (speedup 1.0000x reference)
#include <cuda_runtime.h>

#define B_ 256
#define I_ 512
#define R_ 512
#define A_ 196
#define V_ 10000

// ---------------- scratch (no allocation allowed) ----------------
__device__ float g_ah[B_ * A_];       // [B, A]
__device__ float g_scores[B_ * A_];   // [B, A]
__device__ float g_attres[B_ * R_];   // [B, R]
__device__ float g_sums[B_ * 4 * R_]; // [B, 4R]
__device__ float g_nexth[B_ * R_];    // [B, R]

// ---------------- f32x2 packed helpers ----------------
typedef unsigned long long u64t;

__device__ __forceinline__ u64t fma2(u64t a, u64t b, u64t c) {
    u64t d;
    asm("fma.rn.f32x2 %0, %1, %2, %3;" : "=l"(d) : "l"(a), "l"(b), "l"(c));
    return d;
}
__device__ __forceinline__ u64t pack2(float x, float y) {
    u64t d;
    asm("mov.b64 %0, {%1, %2};" : "=l"(d) : "f"(x), "f"(y));
    return d;
}
__device__ __forceinline__ float2 unpack2(u64t v) {
    float2 r;
    asm("mov.b64 {%0, %1}, %2;" : "=f"(r.x), "=f"(r.y) : "l"(v));
    return r;
}

// ---------------- generic tiled SGEMM 64x64: C[m,n] = sum_k A[m,k]*B[n,k] + b1[n] ----------------
// row-pairs packed naturally from As float4; cols broadcast (4 packs / kk)
__global__ void __launch_bounds__(256, 2) sgemm_bias(
    const float* __restrict__ Am, const float* __restrict__ Bm,
    const float* __restrict__ b1,
    float* __restrict__ C, int M, int N, int K)
{
    __shared__ __align__(16) float As[16][68];
    __shared__ __align__(16) float Bs[16][68];
    const int m0 = blockIdx.y * 64, n0 = blockIdx.x * 64;
    const int tid = threadIdx.x;
    const int tn = tid & 15, tm = tid >> 4;
    const int lrow = tid >> 2, lc = (tid & 3) << 2;

    u64t acc2[2][4];
#pragma unroll
    for (int p = 0; p < 2; p++)
#pragma unroll
        for (int j = 0; j < 4; j++) acc2[p][j] = pack2(0.f, 0.f);

    for (int k0 = 0; k0 < K; k0 += 16) {
        float4 av = make_float4(0.f, 0.f, 0.f, 0.f);
        float4 bv = make_float4(0.f, 0.f, 0.f, 0.f);
        if (m0 + lrow < M) av = *(const float4*)(Am + (size_t)(m0 + lrow) * K + k0 + lc);
        if (n0 + lrow < N) bv = *(const float4*)(Bm + (size_t)(n0 + lrow) * K + k0 + lc);
        __syncthreads();
        As[lc + 0][lrow] = av.x; As[lc + 1][lrow] = av.y; As[lc + 2][lrow] = av.z; As[lc + 3][lrow] = av.w;
        Bs[lc + 0][lrow] = bv.x; Bs[lc + 1][lrow] = bv.y; Bs[lc + 2][lrow] = bv.z; Bs[lc + 3][lrow] = bv.w;
        __syncthreads();
#pragma unroll
        for (int kk = 0; kk < 16; kk++) {
            float4 a4 = *(const float4*)&As[kk][tm << 2];
            float4 b4 = *(const float4*)&Bs[kk][tn << 2];
            u64t ap0 = pack2(a4.x, a4.y);   // rows 2*0, 2*0+1 (natural pair)
            u64t ap1 = pack2(a4.z, a4.w);
            u64t bb0 = pack2(b4.x, b4.x);
            u64t bb1 = pack2(b4.y, b4.y);
            u64t bb2 = pack2(b4.z, b4.z);
            u64t bb3 = pack2(b4.w, b4.w);
            acc2[0][0] = fma2(ap0, bb0, acc2[0][0]);
            acc2[0][1] = fma2(ap0, bb1, acc2[0][1]);
            acc2[0][2] = fma2(ap0, bb2, acc2[0][2]);
            acc2[0][3] = fma2(ap0, bb3, acc2[0][3]);
            acc2[1][0] = fma2(ap1, bb0, acc2[1][0]);
            acc2[1][1] = fma2(ap1, bb1, acc2[1][1]);
            acc2[1][2] = fma2(ap1, bb2, acc2[1][2]);
            acc2[1][3] = fma2(ap1, bb3, acc2[1][3]);
        }
    }
#pragma unroll
    for (int j = 0; j < 4; j++) {
        int n = n0 + (tn << 2) + j;
        if (n >= N) continue;
        float bias = b1 ? b1[n] : 0.f;
#pragma unroll
        for (int p = 0; p < 2; p++) {
            float2 v = unpack2(acc2[p][j]);
            int m = m0 + (tm << 2) + (p << 1);
            if (m < M)     C[(size_t)m * N + n]       = v.x + bias;
            if (m + 1 < M) C[(size_t)(m + 1) * N + n] = v.y + bias;
        }
    }
}

// ---------------- gates: sums = x@Wi^T + h@Wh^T + ar@Wa^T + (bi+bh+ba) ----------------
// tile 64(M) x 32(N) -> grid 64x4 = 256 blocks
__global__ void __launch_bounds__(256, 3) gates_gemm(
    const float* __restrict__ x,  const float* __restrict__ Wi,
    const float* __restrict__ h,  const float* __restrict__ Wh,
    const float* __restrict__ ar, const float* __restrict__ Wa,
    const float* __restrict__ b1, const float* __restrict__ b2, const float* __restrict__ b3)
{
    __shared__ __align__(16) float As[16][68];
    __shared__ __align__(16) float Bs[16][36];
    const int m0 = blockIdx.y * 64, n0 = blockIdx.x * 32;
    const int tid = threadIdx.x;
    const int tn = tid & 15, tm = tid >> 4;
    const int lrow = tid >> 2, lc = (tid & 3) << 2;

    u64t acc2[2][2];
#pragma unroll
    for (int p = 0; p < 2; p++)
#pragma unroll
        for (int j = 0; j < 2; j++) acc2[p][j] = pack2(0.f, 0.f);

#pragma unroll 1
    for (int ph = 0; ph < 3; ph++) {
        const float* Am = (ph == 0) ? x : (ph == 1) ? h : ar;
        const float* Bm = (ph == 0) ? Wi : (ph == 1) ? Wh : Wa;
        for (int k0 = 0; k0 < R_; k0 += 16) {
            float4 av = *(const float4*)(Am + (size_t)(m0 + lrow) * R_ + k0 + lc);
            float4 bv;
            if (tid < 128) bv = *(const float4*)(Bm + (size_t)(n0 + lrow) * R_ + k0 + lc);
            __syncthreads();
            As[lc + 0][lrow] = av.x; As[lc + 1][lrow] = av.y; As[lc + 2][lrow] = av.z; As[lc + 3][lrow] = av.w;
            if (tid < 128) {
                Bs[lc + 0][lrow] = bv.x; Bs[lc + 1][lrow] = bv.y; Bs[lc + 2][lrow] = bv.z; Bs[lc + 3][lrow] = bv.w;
            }
            __syncthreads();
#pragma unroll
            for (int kk = 0; kk < 16; kk++) {
                float4 a4 = *(const float4*)&As[kk][tm << 2];
                float2 b2 = *(const float2*)&Bs[kk][tn << 1];
                u64t ap0 = pack2(a4.x, a4.y);
                u64t ap1 = pack2(a4.z, a4.w);
                u64t bb0 = pack2(b2.x, b2.x);
                u64t bb1 = pack2(b2.y, b2.y);
                acc2[0][0] = fma2(ap0, bb0, acc2[0][0]);
                acc2[0][1] = fma2(ap0, bb1, acc2[0][1]);
                acc2[1][0] = fma2(ap1, bb0, acc2[1][0]);
                acc2[1][1] = fma2(ap1, bb1, acc2[1][1]);
            }
        }
    }
#pragma unroll
    for (int j = 0; j < 2; j++) {
        int n = n0 + (tn << 1) + j;
        float bias = b1[n] + b2[n] + b3[n];
#pragma unroll
        for (int p = 0; p < 2; p++) {
            float2 v = unpack2(acc2[p][j]);
            int m = m0 + (tm << 2) + (p << 1);
            g_sums[(size_t)m * (4 * R_) + n]       = v.x + bias;
            g_sums[(size_t)(m + 1) * (4 * R_) + n] = v.y + bias;
        }
    }
}

// ---------------- fused attend scores ----------------
// M = B*A = 50176 rows, N = 196 (padded 256), K = 512.
// scores[m] = bd + sum_o tanh( att_row[m]·Wa[o] + ba[o] + ah[m] ) * Wd[o]
// col-pairs packed naturally from Bs float4; rows broadcast (4 packs / kk)
__global__ void __launch_bounds__(256, 2) attend_scores(
    const float* __restrict__ att, const float* __restrict__ Wa,
    const float* __restrict__ ba,  const float* __restrict__ Wd,
    const float* __restrict__ bd)
{
    __shared__ __align__(16) float As[16][68];
    __shared__ __align__(16) float Bs[16][260];
    __shared__ float preds[64][17];
    const int m0 = blockIdx.x * 64;
    const int tid = threadIdx.x;
    const int tn = tid & 15, tm = tid >> 4;
    const int lrow = tid >> 2, lc = (tid & 3) << 2;

    u64t acc2[4][8];
#pragma unroll
    for (int i = 0; i < 4; i++)
#pragma unroll
        for (int j = 0; j < 8; j++) acc2[i][j] = pack2(0.f, 0.f);

    for (int k0 = 0; k0 < R_; k0 += 16) {
        float4 av = *(const float4*)(att + (size_t)(m0 + lrow) * R_ + k0 + lc);
        float4 bv[4];
#pragma unroll
        for (int u = 0; u < 4; u++) {
            int br = lrow + (u << 6);
            bv[u] = (br < A_) ? *(const float4*)(Wa + (size_t)br * R_ + k0 + lc)
                              : make_float4(0.f, 0.f, 0.f, 0.f);
        }
        __syncthreads();
        As[lc + 0][lrow] = av.x; As[lc + 1][lrow] = av.y; As[lc + 2][lrow] = av.z; As[lc + 3][lrow] = av.w;
#pragma unroll
        for (int u = 0; u < 4; u++) {
            int br = lrow + (u << 6);
            Bs[lc + 0][br] = bv[u].x; Bs[lc + 1][br] = bv[u].y; Bs[lc + 2][br] = bv[u].z; Bs[lc + 3][br] = bv[u].w;
        }
        __syncthreads();
#pragma unroll
        for (int kk = 0; kk < 16; kk++) {
            float4 a4 = *(const float4*)&As[kk][tm << 2];
            u64t ar0 = pack2(a4.x, a4.x);
            u64t ar1 = pack2(a4.y, a4.y);
            u64t ar2 = pack2(a4.z, a4.z);
            u64t ar3 = pack2(a4.w, a4.w);
#pragma unroll
            for (int ot = 0; ot < 4; ot++) {
                float4 b4 = *(const float4*)&Bs[kk][(ot << 6) + (tn << 2)];
                u64t bp0 = pack2(b4.x, b4.y);   // natural col pair
                u64t bp1 = pack2(b4.z, b4.w);
                acc2[0][(ot << 1) + 0] = fma2(ar0, bp0, acc2[0][(ot << 1) + 0]);
                acc2[0][(ot << 1) + 1] = fma2(ar0, bp1, acc2[0][(ot << 1) + 1]);
                acc2[1][(ot << 1) + 0] = fma2(ar1, bp0, acc2[1][(ot << 1) + 0]);
                acc2[1][(ot << 1) + 1] = fma2(ar1, bp1, acc2[1][(ot << 1) + 1]);
                acc2[2][(ot << 1) + 0] = fma2(ar2, bp0, acc2[2][(ot << 1) + 0]);
                acc2[2][(ot << 1) + 1] = fma2(ar2, bp1, acc2[2][(ot << 1) + 1]);
                acc2[3][(ot << 1) + 0] = fma2(ar3, bp0, acc2[3][(ot << 1) + 0]);
                acc2[3][(ot << 1) + 1] = fma2(ar3, bp1, acc2[3][(ot << 1) + 1]);
            }
        }
    }

    // epilogue: tanh + weighted reduction over o (N dim)
    float ahv[4];
#pragma unroll
    for (int i = 0; i < 4; i++) ahv[i] = g_ah[m0 + (tm << 2) + i];

    float part[4] = {0.f, 0.f, 0.f, 0.f};
#pragma unroll
    for (int ot = 0; ot < 4; ot++)
#pragma unroll
        for (int p = 0; p < 2; p++) {
            int o0 = (ot << 6) + (tn << 2) + (p << 1);
#pragma unroll
            for (int half = 0; half < 2; half++) {
                int o = o0 + half;
                if (o < A_) {
                    float wdo = Wd[o];
                    float bao = ba[o];
#pragma unroll
                    for (int i = 0; i < 4; i++) {
                        float2 v = unpack2(acc2[i][(ot << 1) + p]);
                        float s = half ? v.y : v.x;
                        part[i] += tanhf(s + bao + ahv[i]) * wdo;
                    }
                }
            }
        }
#pragma unroll
    for (int i = 0; i < 4; i++) preds[(tm << 2) + i][tn] = part[i];
    __syncthreads();
    if (tid < 64) {
        float s = bd[0];
#pragma unroll
        for (int t = 0; t < 16; t++) s += preds[tid][t];
        g_scores[m0 + tid] = s;
    }
}

// ---------------- softmax over a + weighted sum of att rows ----------------
__global__ void attend_apply(const float* __restrict__ att, float* __restrict__ outres)
{
    const int b = blockIdx.x, tid = threadIdx.x;  // 256 threads
    __shared__ float w[A_];
    __shared__ float rbuf[256];

    float s = (tid < A_) ? g_scores[b * A_ + tid] : -1e30f;
    rbuf[tid] = s;
    __syncthreads();
    for (int off = 128; off > 0; off >>= 1) {
        if (tid < off) rbuf[tid] = fmaxf(rbuf[tid], rbuf[tid + off]);
        __syncthreads();
    }
    float mx = rbuf[0];
    __syncthreads();
    float e = (tid < A_) ? __expf(s - mx) : 0.f;
    rbuf[tid] = e;
    __syncthreads();
    for (int off = 128; off > 0; off >>= 1) {
        if (tid < off) rbuf[tid] += rbuf[tid + off];
        __syncthreads();
    }
    float inv = 1.f / rbuf[0];
    if (tid < A_) w[tid] = e * inv;
    __syncthreads();

    const float* ab = att + (size_t)b * A_ * R_;
    for (int r = tid; r < R_; r += 256) {
        float acc = 0.f;
#pragma unroll 4
        for (int a = 0; a < A_; a++) acc += ab[a * R_ + r] * w[a];
        outres[b * R_ + r] = acc;
    }
}

// ---------------- LSTM cell ----------------
__global__ void lstm_cell(const float* __restrict__ prev_c, float* __restrict__ out_c)
{
    int idx = blockIdx.x * 256 + threadIdx.x;
    if (idx >= B_ * R_) return;
    int b = idx >> 9, j = idx & (R_ - 1);
    const float* s = g_sums + (size_t)b * 4 * R_;
    float ig = 1.f / (1.f + __expf(-s[j]));
    float fg = 1.f / (1.f + __expf(-s[R_ + j]));
    float og = 1.f / (1.f + __expf(-s[2 * R_ + j]));
    float gt = tanhf(s[3 * R_ + j]);
    float c = fg * prev_c[idx] + ig * gt;
    out_c[idx] = c;
    g_nexth[idx] = og * tanhf(c);
}

// ---------------- top_h = attres + next_h ----------------
__global__ void add_toph(float* __restrict__ out_h)
{
    int idx = blockIdx.x * 256 + threadIdx.x;
    if (idx >= B_ * R_) return;
    out_h[idx] = g_attres[idx] + g_nexth[idx];
}

// ---------------- log_softmax in-place over V ----------------
__global__ void log_softmax_kernel(float* __restrict__ logits)
{
    const int b = blockIdx.x, tid = threadIdx.x;  // 512 threads
    float* row = logits + (size_t)b * V_;
    __shared__ float rbuf[512];

    float mx = -1e30f;
    for (int i = tid; i < V_; i += 512) mx = fmaxf(mx, row[i]);
    rbuf[tid] = mx;
    __syncthreads();
    for (int off = 256; off > 0; off >>= 1) {
        if (tid < off) rbuf[tid] = fmaxf(rbuf[tid], rbuf[tid + off]);
        __syncthreads();
    }
    mx = rbuf[0];
    __syncthreads();
    float sum = 0.f;
    for (int i = tid; i < V_; i += 512) sum += __expf(row[i] - mx);
    rbuf[tid] = sum;
    __syncthreads();
    for (int off = 256; off > 0; off >>= 1) {
        if (tid < off) rbuf[tid] += rbuf[tid + off];
        __syncthreads();
    }
    float lse = mx + logf(rbuf[0]);
    for (int i = tid; i < V_; i += 512) row[i] -= lse;
}

// ---------------- host launch ----------------
extern "C" void kernel_launch(void* const* d_in, const int* in_sizes, int n_in,
                              void* d_out, int out_size)
{
    const float* x      = (const float*)d_in[0];
    const float* att    = (const float*)d_in[1];
    const float* prev_c = (const float*)d_in[2];
    const float* prev_h = (const float*)d_in[3];
    const float* W_a2a  = (const float*)d_in[4];  const float* b_a2a  = (const float*)d_in[5];
    const float* W_h2a  = (const float*)d_in[6];  const float* b_h2a  = (const float*)d_in[7];
    const float* W_d2d  = (const float*)d_in[8];  const float* b_d2d  = (const float*)d_in[9];
    const float* W_i2h  = (const float*)d_in[10]; const float* b_i2h  = (const float*)d_in[11];
    const float* W_a2h  = (const float*)d_in[12]; const float* b_a2h  = (const float*)d_in[13];
    const float* W_h2h  = (const float*)d_in[14]; const float* b_h2h  = (const float*)d_in[15];
    const float* W_a2a1 = (const float*)d_in[16]; const float* b_a2a1 = (const float*)d_in[17];
    const float* W_h2a1 = (const float*)d_in[18]; const float* b_h2a1 = (const float*)d_in[19];
    const float* W_d2d1 = (const float*)d_in[20]; const float* b_d2d1 = (const float*)d_in[21];
    const float* W_proj = (const float*)d_in[22]; const float* b_proj = (const float*)d_in[23];

    float* out   = (float*)d_out;
    float* out_c = out;                  // next_c  [B,R]
    float* out_h = out + B_ * R_;        // top_h   [B,R]
    float* out_l = out + 2 * B_ * R_;    // logsoft [B,V]

    float *ah_p, *attres_p, *nexth_p;
    cudaGetSymbolAddress((void**)&ah_p,     g_ah);
    cudaGetSymbolAddress((void**)&attres_p, g_attres);
    cudaGetSymbolAddress((void**)&nexth_p,  g_nexth);

    const dim3 blk(256);

    // ---- attend #0 (uses prev_h) ----
    sgemm_bias<<<dim3((A_ + 63) / 64, (B_ + 63) / 64), blk>>>(prev_h, W_h2a, b_h2a, ah_p, B_, A_, R_);
    attend_scores<<<(B_ * A_) / 64, blk>>>(att, W_a2a, b_a2a, W_d2d, b_d2d);
    attend_apply<<<B_, blk>>>(att, attres_p);

    // ---- LSTM gates ----
    gates_gemm<<<dim3((4 * R_) / 32, B_ / 64), blk>>>(x, W_i2h, prev_h, W_h2h, attres_p, W_a2h,
                                                      b_i2h, b_h2h, b_a2h);
    lstm_cell<<<(B_ * R_ + 255) / 256, blk>>>(prev_c, out_c);

    // ---- attend #1 (uses next_h) ----
    sgemm_bias<<<dim3((A_ + 63) / 64, (B_ + 63) / 64), blk>>>(nexth_p, W_h2a1, b_h2a1, ah_p, B_, A_, R_);
    attend_scores<<<(B_ * A_) / 64, blk>>>(att, W_a2a1, b_a2a1, W_d2d1, b_d2d1);
    attend_apply<<<B_, blk>>>(att, attres_p);

    // ---- top_h, projection, log_softmax ----
    add_toph<<<(B_ * R_ + 255) / 256, blk>>>(out_h);
    sgemm_bias<<<dim3((V_ + 63) / 64, (B_ + 63) / 64), blk>>>(out_h, W_proj, b_proj, out_l, B_, V_, R_);
    log_softmax_kernel<<<B_, 512>>>(out_l);
}

// round 4
// speedup vs baseline: 1.3381x; 1.3381x over previous
#include <cuda_runtime.h>
#include <cuda_bf16.h>
#include <mma.h>
#include <cstdint>

using namespace nvcuda;

#define B_ 256
#define I_ 512
#define R_ 512
#define A_ 196
#define V_ 10000

// ================= scratch (static device; no allocation allowed) =================
__device__ float g_ah[B_ * A_];          // [B, A]
__device__ float g_spart[B_ * A_ * 4];   // score partials: 2 ntiles x 2 col-halves
__device__ float g_attres[B_ * R_];      // [B, R]
__device__ float g_sums[B_ * 4 * R_];    // [B, 4R] raw gate GEMM (bias added in lstm_cell)
__device__ float g_nexth[B_ * R_];       // [B, R]
__device__ float g_bias[4 * R_];         // combined gate bias

// split-bf16 weight caches
__device__ __nv_bfloat16 g_Wa2a_h[A_ * R_],  g_Wa2a_l[A_ * R_];
__device__ __nv_bfloat16 g_Wa2a1_h[A_ * R_], g_Wa2a1_l[A_ * R_];
__device__ __nv_bfloat16 g_Wi_h[4 * R_ * I_], g_Wi_l[4 * R_ * I_];
__device__ __nv_bfloat16 g_Wh_h[4 * R_ * R_], g_Wh_l[4 * R_ * R_];
__device__ __nv_bfloat16 g_Wah_h[4 * R_ * R_], g_Wah_l[4 * R_ * R_];
__device__ __nv_bfloat16 g_Wp_h[V_ * R_], g_Wp_l[V_ * R_];

// smem staging layout in bf16 elements (ld = 40)
#define LDT 40
#define OFF_AH 0
#define OFF_AL 5120
#define OFF_BH 10240
#define OFF_BL 15360
#define SMEM_MODE0 40960
#define SMEM_MODE1 69632   // 128 x 132 fp32 C tile (67584) rounded up

__device__ __forceinline__ void split_store(__nv_bfloat16* hi, __nv_bfloat16* lo, float v) {
    __nv_bfloat16 h = __float2bfloat16_rn(v);
    *hi = h;
    *lo = __float2bfloat16_rn(v - __bfloat162float(h));
}

// ================= split-bf16 HMMA GEMM =================
// C[m0..m0+127, n0..n0+255... (128 wide)] = sum_ph A_ph[m,:512] . B_ph[n,:512]^T
// MODE 0: out[m*ldout + n] = C (store skipped where n-frag exceeds Ntot; Ntot % 16 == 0)
// MODE 1: g_spart[m*4 + ntile*2 + half] = sum_{o in half} tanh(C[m,o]+ba[o]+g_ah[m])*Wd[o]
template <int MODE>
__global__ void __launch_bounds__(256, 2) tc_gemm(
    const float* __restrict__ A0, const float* __restrict__ A1, const float* __restrict__ A2,
    const __nv_bfloat16* __restrict__ Bh0, const __nv_bfloat16* __restrict__ Bl0,
    const __nv_bfloat16* __restrict__ Bh1, const __nv_bfloat16* __restrict__ Bl1,
    const __nv_bfloat16* __restrict__ Bh2, const __nv_bfloat16* __restrict__ Bl2,
    int nph, int Ntot,
    float* __restrict__ out, int ldout,
    const float* __restrict__ ba, const float* __restrict__ Wd)
{
    extern __shared__ char smem[];
    __nv_bfloat16* sAH = (__nv_bfloat16*)smem + OFF_AH;
    __nv_bfloat16* sAL = (__nv_bfloat16*)smem + OFF_AL;
    __nv_bfloat16* sBH = (__nv_bfloat16*)smem + OFF_BH;
    __nv_bfloat16* sBL = (__nv_bfloat16*)smem + OFF_BL;

    const int tid = threadIdx.x;
    const int wid = tid >> 5;
    const int wm = wid >> 2, wn = wid & 3;       // 2 x 4 warp grid
    const int m0 = blockIdx.y * 128, n0 = blockIdx.x * 128;

    wmma::fragment<wmma::accumulator, 16, 16, 16, float> acc[4][2];
#pragma unroll
    for (int i = 0; i < 4; i++)
#pragma unroll
        for (int j = 0; j < 2; j++) wmma::fill_fragment(acc[i][j], 0.0f);

    const int r  = tid >> 1;               // 0..127
    const int ch = (tid & 1) * 16;         // col half within 32-chunk

    for (int ph = 0; ph < nph; ph++) {
        const float* Ap = (ph == 0) ? A0 : (ph == 1) ? A1 : A2;
        const __nv_bfloat16* Bh = (ph == 0) ? Bh0 : (ph == 1) ? Bh1 : Bh2;
        const __nv_bfloat16* Bl = (ph == 0) ? Bl0 : (ph == 1) ? Bl1 : Bl2;

        for (int k0 = 0; k0 < 512; k0 += 32) {
            __syncthreads();
            // ---- fill A: fp32 -> split bf16, 128 rows x 32 cols ----
            {
                const float4* src = (const float4*)(Ap + (size_t)(m0 + r) * 512 + k0 + ch);
#pragma unroll
                for (int q = 0; q < 4; q++) {
                    float4 v = src[q];
                    int base = r * LDT + ch + q * 4;
                    split_store(sAH + base + 0, sAL + base + 0, v.x);
                    split_store(sAH + base + 1, sAL + base + 1, v.y);
                    split_store(sAH + base + 2, sAL + base + 2, v.z);
                    split_store(sAH + base + 3, sAL + base + 3, v.w);
                }
            }
            // ---- fill B: pre-split bf16 copy, 128 rows x 32 cols ----
            {
                const int Brow = n0 + r;
                if (Brow < Ntot) {
                    const uint4* sh = (const uint4*)(Bh + (size_t)Brow * 512 + k0 + ch);
                    const uint4* sl = (const uint4*)(Bl + (size_t)Brow * 512 + k0 + ch);
                    *(uint4*)(sBH + r * LDT + ch)     = sh[0];
                    *(uint4*)(sBH + r * LDT + ch + 8) = sh[1];
                    *(uint4*)(sBL + r * LDT + ch)     = sl[0];
                    *(uint4*)(sBL + r * LDT + ch + 8) = sl[1];
                } else {
                    const uint4 z = make_uint4(0, 0, 0, 0);
                    *(uint4*)(sBH + r * LDT + ch)     = z;
                    *(uint4*)(sBH + r * LDT + ch + 8) = z;
                    *(uint4*)(sBL + r * LDT + ch)     = z;
                    *(uint4*)(sBL + r * LDT + ch + 8) = z;
                }
            }
            __syncthreads();

#pragma unroll
            for (int ks = 0; ks < 2; ks++) {
                wmma::fragment<wmma::matrix_a, 16, 16, 16, __nv_bfloat16, wmma::row_major> fah[4], fal[4];
#pragma unroll
                for (int i = 0; i < 4; i++) {
                    wmma::load_matrix_sync(fah[i], sAH + (wm * 64 + i * 16) * LDT + ks * 16, LDT);
                    wmma::load_matrix_sync(fal[i], sAL + (wm * 64 + i * 16) * LDT + ks * 16, LDT);
                }
#pragma unroll
                for (int j = 0; j < 2; j++) {
                    wmma::fragment<wmma::matrix_b, 16, 16, 16, __nv_bfloat16, wmma::col_major> fbh, fbl;
                    wmma::load_matrix_sync(fbh, sBH + (wn * 32 + j * 16) * LDT + ks * 16, LDT);
                    wmma::load_matrix_sync(fbl, sBL + (wn * 32 + j * 16) * LDT + ks * 16, LDT);
#pragma unroll
                    for (int i = 0; i < 4; i++) {
                        wmma::mma_sync(acc[i][j], fah[i], fbh, acc[i][j]);
                        wmma::mma_sync(acc[i][j], fah[i], fbl, acc[i][j]);
                        wmma::mma_sync(acc[i][j], fal[i], fbh, acc[i][j]);
                    }
                }
            }
        }
    }

    if constexpr (MODE == 0) {
#pragma unroll
        for (int i = 0; i < 4; i++) {
            int mrow = m0 + wm * 64 + i * 16;
#pragma unroll
            for (int j = 0; j < 2; j++) {
                int ncol = n0 + wn * 32 + j * 16;
                if (ncol + 16 <= Ntot)
                    wmma::store_matrix_sync(out + (size_t)mrow * ldout + ncol, acc[i][j],
                                            ldout, wmma::mem_row_major);
            }
        }
    } else {
        // store C tile to smem (union with staging), then tanh-reduce
        __syncthreads();
        float* Cs = (float*)smem;   // [128][132]
#pragma unroll
        for (int i = 0; i < 4; i++)
#pragma unroll
            for (int j = 0; j < 2; j++)
                wmma::store_matrix_sync(Cs + (wm * 64 + i * 16) * 132 + wn * 32 + j * 16,
                                        acc[i][j], 132, wmma::mem_row_major);
        __syncthreads();
        const int half = tid & 1;
        const int c0 = half * 64;
        float ahm = g_ah[m0 + r];
        float p = 0.f;
#pragma unroll 4
        for (int c = 0; c < 64; c++) {
            int o = n0 + c0 + c;
            if (o < Ntot)
                p += tanhf(Cs[r * 132 + c0 + c] + ba[o] + ahm) * Wd[o];
        }
        g_spart[(size_t)(m0 + r) * 4 + blockIdx.x * 2 + half] = p;
    }
}

// ================= weight fp32 -> split bf16 =================
__global__ void conv_split(const float* __restrict__ src, __nv_bfloat16* __restrict__ hi,
                           __nv_bfloat16* __restrict__ lo, int n4)
{
    int i = blockIdx.x * 256 + threadIdx.x;
    if (i >= n4) return;
    float4 v = ((const float4*)src)[i];
    __nv_bfloat16 hx = __float2bfloat16_rn(v.x), hy = __float2bfloat16_rn(v.y);
    __nv_bfloat16 hz = __float2bfloat16_rn(v.z), hw = __float2bfloat16_rn(v.w);
    __nv_bfloat16 lx = __float2bfloat16_rn(v.x - __bfloat162float(hx));
    __nv_bfloat16 ly = __float2bfloat16_rn(v.y - __bfloat162float(hy));
    __nv_bfloat16 lz = __float2bfloat16_rn(v.z - __bfloat162float(hz));
    __nv_bfloat16 lw = __float2bfloat16_rn(v.w - __bfloat162float(hw));
    uint2 H, L;
    H.x = (uint32_t)__bfloat16_as_ushort(hx) | ((uint32_t)__bfloat16_as_ushort(hy) << 16);
    H.y = (uint32_t)__bfloat16_as_ushort(hz) | ((uint32_t)__bfloat16_as_ushort(hw) << 16);
    L.x = (uint32_t)__bfloat16_as_ushort(lx) | ((uint32_t)__bfloat16_as_ushort(ly) << 16);
    L.y = (uint32_t)__bfloat16_as_ushort(lz) | ((uint32_t)__bfloat16_as_ushort(lw) << 16);
    ((uint2*)hi)[i] = H;
    ((uint2*)lo)[i] = L;
}

__global__ void bias_sum(const float* __restrict__ b1, const float* __restrict__ b2,
                         const float* __restrict__ b3)
{
    int i = blockIdx.x * 256 + threadIdx.x;
    if (i < 4 * R_) g_bias[i] = b1[i] + b2[i] + b3[i];
}

// ================= SIMT sgemm for the small ah projection =================
__global__ void __launch_bounds__(256, 2) sgemm_bias(
    const float* __restrict__ Am, const float* __restrict__ Bm,
    const float* __restrict__ b1,
    float* __restrict__ C, int M, int N, int K)
{
    __shared__ __align__(16) float As[16][68];
    __shared__ __align__(16) float Bs[16][68];
    const int m0 = blockIdx.y * 64, n0 = blockIdx.x * 64;
    const int tid = threadIdx.x;
    const int tn = tid & 15, tm = tid >> 4;
    const int lrow = tid >> 2, lc = (tid & 3) << 2;

    float acc[4][4] = {};
    for (int k0 = 0; k0 < K; k0 += 16) {
        float4 av = make_float4(0.f, 0.f, 0.f, 0.f);
        float4 bv = make_float4(0.f, 0.f, 0.f, 0.f);
        if (m0 + lrow < M) av = *(const float4*)(Am + (size_t)(m0 + lrow) * K + k0 + lc);
        if (n0 + lrow < N) bv = *(const float4*)(Bm + (size_t)(n0 + lrow) * K + k0 + lc);
        __syncthreads();
        As[lc + 0][lrow] = av.x; As[lc + 1][lrow] = av.y; As[lc + 2][lrow] = av.z; As[lc + 3][lrow] = av.w;
        Bs[lc + 0][lrow] = bv.x; Bs[lc + 1][lrow] = bv.y; Bs[lc + 2][lrow] = bv.z; Bs[lc + 3][lrow] = bv.w;
        __syncthreads();
#pragma unroll
        for (int kk = 0; kk < 16; kk++) {
            float a[4], b[4];
            *(float4*)a = *(const float4*)&As[kk][tm << 2];
            *(float4*)b = *(const float4*)&Bs[kk][tn << 2];
#pragma unroll
            for (int i = 0; i < 4; i++)
#pragma unroll
                for (int j = 0; j < 4; j++)
                    acc[i][j] += a[i] * b[j];
        }
    }
#pragma unroll
    for (int j = 0; j < 4; j++) {
        int n = n0 + (tn << 2) + j;
        if (n >= N) continue;
        float bias = b1 ? b1[n] : 0.f;
#pragma unroll
        for (int i = 0; i < 4; i++) {
            int m = m0 + (tm << 2) + i;
            if (m < M) C[(size_t)m * N + n] = acc[i][j] + bias;
        }
    }
}

// ================= softmax over a + weighted sum of att rows =================
__global__ void attend_apply(const float* __restrict__ att, float* __restrict__ outres,
                             const float* __restrict__ bd)
{
    const int b = blockIdx.x, tid = threadIdx.x;  // 256 threads
    __shared__ float w[A_];
    __shared__ float rbuf[256];

    float s = -1e30f;
    if (tid < A_) {
        const float* p = &g_spart[(size_t)(b * A_ + tid) * 4];
        s = bd[0] + p[0] + p[1] + p[2] + p[3];
    }
    rbuf[tid] = s;
    __syncthreads();
    for (int off = 128; off > 0; off >>= 1) {
        if (tid < off) rbuf[tid] = fmaxf(rbuf[tid], rbuf[tid + off]);
        __syncthreads();
    }
    float mx = rbuf[0];
    __syncthreads();
    float e = (tid < A_) ? __expf(s - mx) : 0.f;
    rbuf[tid] = e;
    __syncthreads();
    for (int off = 128; off > 0; off >>= 1) {
        if (tid < off) rbuf[tid] += rbuf[tid + off];
        __syncthreads();
    }
    float inv = 1.f / rbuf[0];
    if (tid < A_) w[tid] = e * inv;
    __syncthreads();

    const float* ab = att + (size_t)b * A_ * R_;
    for (int r = tid; r < R_; r += 256) {
        float acc = 0.f;
#pragma unroll 4
        for (int a = 0; a < A_; a++) acc += ab[a * R_ + r] * w[a];
        outres[b * R_ + r] = acc;
    }
}

// ================= LSTM cell (adds combined gate bias) =================
__global__ void lstm_cell(const float* __restrict__ prev_c, float* __restrict__ out_c)
{
    int idx = blockIdx.x * 256 + threadIdx.x;
    if (idx >= B_ * R_) return;
    int b = idx >> 9, j = idx & (R_ - 1);
    const float* s = g_sums + (size_t)b * 4 * R_;
    float ig = 1.f / (1.f + __expf(-(s[j] + g_bias[j])));
    float fg = 1.f / (1.f + __expf(-(s[R_ + j] + g_bias[R_ + j])));
    float og = 1.f / (1.f + __expf(-(s[2 * R_ + j] + g_bias[2 * R_ + j])));
    float gt = tanhf(s[3 * R_ + j] + g_bias[3 * R_ + j]);
    float c = fg * prev_c[idx] + ig * gt;
    out_c[idx] = c;
    g_nexth[idx] = og * tanhf(c);
}

__global__ void add_toph(float* __restrict__ out_h)
{
    int idx = blockIdx.x * 256 + threadIdx.x;
    if (idx >= B_ * R_) return;
    out_h[idx] = g_attres[idx] + g_nexth[idx];
}

// ================= log_softmax (adds proj bias, in-place normalize) =================
__global__ void log_softmax_kernel(float* __restrict__ logits, const float* __restrict__ bias)
{
    const int b = blockIdx.x, tid = threadIdx.x;  // 512 threads
    float* row = logits + (size_t)b * V_;
    __shared__ float rbuf[512];

    float mx = -1e30f;
    for (int i = tid; i < V_; i += 512) mx = fmaxf(mx, row[i] + bias[i]);
    rbuf[tid] = mx;
    __syncthreads();
    for (int off = 256; off > 0; off >>= 1) {
        if (tid < off) rbuf[tid] = fmaxf(rbuf[tid], rbuf[tid + off]);
        __syncthreads();
    }
    mx = rbuf[0];
    __syncthreads();
    float sum = 0.f;
    for (int i = tid; i < V_; i += 512) sum += __expf(row[i] + bias[i] - mx);
    rbuf[tid] = sum;
    __syncthreads();
    for (int off = 256; off > 0; off >>= 1) {
        if (tid < off) rbuf[tid] += rbuf[tid + off];
        __syncthreads();
    }
    float lse = mx + logf(rbuf[0]);
    for (int i = tid; i < V_; i += 512) row[i] = row[i] + bias[i] - lse;
}

// ================= host launch =================
extern "C" void kernel_launch(void* const* d_in, const int* in_sizes, int n_in,
                              void* d_out, int out_size)
{
    const float* x      = (const float*)d_in[0];
    const float* att    = (const float*)d_in[1];
    const float* prev_c = (const float*)d_in[2];
    const float* prev_h = (const float*)d_in[3];
    const float* W_a2a  = (const float*)d_in[4];  const float* b_a2a  = (const float*)d_in[5];
    const float* W_h2a  = (const float*)d_in[6];  const float* b_h2a  = (const float*)d_in[7];
    const float* W_d2d  = (const float*)d_in[8];  const float* b_d2d  = (const float*)d_in[9];
    const float* W_i2h  = (const float*)d_in[10]; const float* b_i2h  = (const float*)d_in[11];
    const float* W_a2h  = (const float*)d_in[12]; const float* b_a2h  = (const float*)d_in[13];
    const float* W_h2h  = (const float*)d_in[14]; const float* b_h2h  = (const float*)d_in[15];
    const float* W_a2a1 = (const float*)d_in[16]; const float* b_a2a1 = (const float*)d_in[17];
    const float* W_h2a1 = (const float*)d_in[18]; const float* b_h2a1 = (const float*)d_in[19];
    const float* W_d2d1 = (const float*)d_in[20]; const float* b_d2d1 = (const float*)d_in[21];
    const float* W_proj = (const float*)d_in[22]; const float* b_proj = (const float*)d_in[23];

    float* out   = (float*)d_out;
    float* out_c = out;                  // next_c  [B,R]
    float* out_h = out + B_ * R_;        // top_h   [B,R]
    float* out_l = out + 2 * B_ * R_;    // logsoft [B,V]

    float *ah_p, *attres_p, *nexth_p, *sums_p;
    cudaGetSymbolAddress((void**)&ah_p,     g_ah);
    cudaGetSymbolAddress((void**)&attres_p, g_attres);
    cudaGetSymbolAddress((void**)&nexth_p,  g_nexth);
    cudaGetSymbolAddress((void**)&sums_p,   g_sums);

    __nv_bfloat16 *Wa2a_h, *Wa2a_l, *Wa2a1_h, *Wa2a1_l, *Wi_h, *Wi_l, *Wh_h, *Wh_l, *Wah_h, *Wah_l, *Wp_h, *Wp_l;
    cudaGetSymbolAddress((void**)&Wa2a_h,  g_Wa2a_h);  cudaGetSymbolAddress((void**)&Wa2a_l,  g_Wa2a_l);
    cudaGetSymbolAddress((void**)&Wa2a1_h, g_Wa2a1_h); cudaGetSymbolAddress((void**)&Wa2a1_l, g_Wa2a1_l);
    cudaGetSymbolAddress((void**)&Wi_h,    g_Wi_h);    cudaGetSymbolAddress((void**)&Wi_l,    g_Wi_l);
    cudaGetSymbolAddress((void**)&Wh_h,    g_Wh_h);    cudaGetSymbolAddress((void**)&Wh_l,    g_Wh_l);
    cudaGetSymbolAddress((void**)&Wah_h,   g_Wah_h);   cudaGetSymbolAddress((void**)&Wah_l,   g_Wah_l);
    cudaGetSymbolAddress((void**)&Wp_h,    g_Wp_h);    cudaGetSymbolAddress((void**)&Wp_l,    g_Wp_l);

    cudaFuncSetAttribute(tc_gemm<0>, cudaFuncAttributeMaxDynamicSharedMemorySize, SMEM_MODE1);
    cudaFuncSetAttribute(tc_gemm<1>, cudaFuncAttributeMaxDynamicSharedMemorySize, SMEM_MODE1);

    const dim3 blk(256);

    // ---- weight conversion (inputs may change per call) ----
    conv_split<<<(A_ * R_ / 4 + 255) / 256, blk>>>(W_a2a,  Wa2a_h,  Wa2a_l,  A_ * R_ / 4);
    conv_split<<<(A_ * R_ / 4 + 255) / 256, blk>>>(W_a2a1, Wa2a1_h, Wa2a1_l, A_ * R_ / 4);
    conv_split<<<(4 * R_ * I_ / 4 + 255) / 256, blk>>>(W_i2h, Wi_h, Wi_l, 4 * R_ * I_ / 4);
    conv_split<<<(4 * R_ * R_ / 4 + 255) / 256, blk>>>(W_h2h, Wh_h, Wh_l, 4 * R_ * R_ / 4);
    conv_split<<<(4 * R_ * R_ / 4 + 255) / 256, blk>>>(W_a2h, Wah_h, Wah_l, 4 * R_ * R_ / 4);
    conv_split<<<(V_ * R_ / 4 + 255) / 256, blk>>>(W_proj, Wp_h, Wp_l, V_ * R_ / 4);
    bias_sum<<<(4 * R_ + 255) / 256, blk>>>(b_i2h, b_h2h, b_a2h);

    // ---- attend #0 (uses prev_h) ----
    sgemm_bias<<<dim3((A_ + 63) / 64, (B_ + 63) / 64), blk>>>(prev_h, W_h2a, b_h2a, ah_p, B_, A_, R_);
    tc_gemm<1><<<dim3(2, (B_ * A_) / 128), blk, SMEM_MODE1>>>(
        att, nullptr, nullptr, Wa2a_h, Wa2a_l, nullptr, nullptr, nullptr, nullptr,
        1, A_, nullptr, 0, b_a2a, W_d2d);
    attend_apply<<<B_, blk>>>(att, attres_p, b_d2d);

    // ---- LSTM gates (3-phase GEMM) + cell ----
    tc_gemm<0><<<dim3(16, 2), blk, SMEM_MODE0>>>(
        x, prev_h, attres_p, Wi_h, Wi_l, Wh_h, Wh_l, Wah_h, Wah_l,
        3, 4 * R_, sums_p, 4 * R_, nullptr, nullptr);
    lstm_cell<<<(B_ * R_ + 255) / 256, blk>>>(prev_c, out_c);

    // ---- attend #1 (uses next_h) ----
    sgemm_bias<<<dim3((A_ + 63) / 64, (B_ + 63) / 64), blk>>>(nexth_p, W_h2a1, b_h2a1, ah_p, B_, A_, R_);
    tc_gemm<1><<<dim3(2, (B_ * A_) / 128), blk, SMEM_MODE1>>>(
        att, nullptr, nullptr, Wa2a1_h, Wa2a1_l, nullptr, nullptr, nullptr, nullptr,
        1, A_, nullptr, 0, b_a2a1, W_d2d1);
    attend_apply<<<B_, blk>>>(att, attres_p, b_d2d1);

    // ---- top_h, projection, log_softmax ----
    add_toph<<<(B_ * R_ + 255) / 256, blk>>>(out_h);
    tc_gemm<0><<<dim3((V_ + 127) / 128, 2), blk, SMEM_MODE0>>>(
        out_h, nullptr, nullptr, Wp_h, Wp_l, nullptr, nullptr, nullptr, nullptr,
        1, V_, out_l, V_, nullptr, nullptr);
    log_softmax_kernel<<<B_, 512>>>(out_l, b_proj);
}